// round 10
// baseline (speedup 1.0000x reference)
#include <cuda_runtime.h>
#include <math.h>

// Problem constants
#define BB   32
#define LL   2048
#define DIN  64
#define NC   32
#define DC   16
#define OUTD 512           // NC*DC
#define EPSQ 1e-7f

#define K1_CHUNKS 16
#define K3_CHUNKS 8        // blocks per batch in routing pass (256 l's each)
#define K3_WARPS  4
#define K3_LPW    64       // l's per warp

// Scratch (static device allocations only — no cudaMalloc allowed)
__device__ float g_colsum_part[BB][K1_CHUNKS][DIN];
__device__ float g_s_part[BB][K3_CHUNKS][NC][DIN];   // 2 MB, reused by both k3 launches
__device__ float g_v[BB][NC][DIN];
__device__ int   g_cnt1[BB];         // zero-init; reset by last block each launch
__device__ int   g_cnt3[2][BB];

// ---------------------------------------------------------------------------
// K1: column-sum partials + tail epilogue (v0) by the last block of batch b.
// grid (K1_CHUNKS, BB), 256 threads
// ---------------------------------------------------------------------------
__global__ void k1_colsum(const float* __restrict__ u, const float* __restrict__ W) {
    const int b = blockIdx.y, chunk = blockIdx.x;
    const int tid = threadIdx.x;
    const int col4 = tid & 15;
    const int g    = tid >> 4;

    const float4* up = (const float4*)(u + ((size_t)b * LL + (size_t)chunk * 128) * DIN);
    float4 acc = make_float4(0.f, 0.f, 0.f, 0.f);
    #pragma unroll
    for (int r = 0; r < 8; r++) {
        float4 x = up[(size_t)(g + r * 16) * 16 + col4];
        acc.x += x.x; acc.y += x.y; acc.z += x.z; acc.w += x.w;
    }
    __shared__ __align__(16) float4 red[16][16];
    red[g][col4] = acc;
    __syncthreads();
    if (tid < 16) {
        float4 s = red[0][tid];
        #pragma unroll
        for (int i = 1; i < 16; i++) {
            float4 x = red[i][tid];
            s.x += x.x; s.y += x.y; s.z += x.z; s.w += x.w;
        }
        ((float4*)g_colsum_part[b][chunk])[tid] = s;
    }

    // ---- last-block tail: compute v0 for batch b ----
    __shared__ int amLast;
    __threadfence();
    __syncthreads();
    if (tid == 0) amLast = (atomicAdd(&g_cnt1[b], 1) == K1_CHUNKS - 1);
    __syncthreads();
    if (!amLast) return;

    __shared__ __align__(16) float s_sm[DIN];
    __shared__ __align__(16) float raw_sm[OUTD];
    __shared__ float norm_sm[NC];

    if (tid < DIN) {
        float a = 0.f;
        #pragma unroll
        for (int c = 0; c < K1_CHUNKS; c++) a += g_colsum_part[b][c][tid];
        s_sm[tid] = a * (1.0f / 32.0f);       // uniform c = 1/32, same for all n
    }
    __syncthreads();
    for (int o = tid; o < OUTD; o += 256) {   // coalesced over o
        float r = 0.f;
        #pragma unroll
        for (int i = 0; i < DIN; i++)
            r = fmaf(s_sm[i], W[(size_t)i * OUTD + o], r);
        raw_sm[o] = r;
    }
    __syncthreads();
    if (tid < NC) {
        float s2 = 0.f;
        #pragma unroll
        for (int d = 0; d < DC; d++) {
            float r = raw_sm[tid * DC + d];
            s2 = fmaf(r, r, s2);
        }
        norm_sm[tid] = rsqrtf(s2 + EPSQ);
    }
    __syncthreads();
    for (int e = tid; e < NC * DIN; e += 256) {
        const int n = e >> 6, i = e & 63;
        const float4* Wr = (const float4*)(W + (size_t)i * OUTD + n * DC);
        const float4* Rr = (const float4*)(raw_sm + n * DC);
        float r = 0.f;
        #pragma unroll
        for (int q = 0; q < 4; q++) {
            float4 wv = Wr[q], rv = Rr[q];
            r = fmaf(wv.x, rv.x, r); r = fmaf(wv.y, rv.y, r);
            r = fmaf(wv.z, rv.z, r); r = fmaf(wv.w, rv.w, r);
        }
        g_v[b][n][i] = r * norm_sm[n];
    }
    if (tid == 0) g_cnt1[b] = 0;             // reset for next graph replay
}

// ---------------------------------------------------------------------------
// K3: routing pass (proven R7 mainloop) + last-block tail epilogue.
// iter==1: tail computes v1 -> g_v. iter==2: tail writes final out -> d_out.
// grid (K3_CHUNKS, BB), 128 threads (4 warps, 64 l's each).
// ---------------------------------------------------------------------------
__global__ void __launch_bounds__(128, 1) k3_route(const float* __restrict__ u,
                                                   const float* __restrict__ W,
                                                   float* __restrict__ out_final,
                                                   int iter) {
    const int b = blockIdx.y, chunk = blockIdx.x;
    const int t = threadIdx.x;
    const int w = t >> 5;
    const int lane = t & 31;       // lane == capsule index n

    __shared__ __align__(16) float u_buf[K3_WARPS][2][64];
    __shared__ __align__(16) float s_blk[K3_WARPS][NC][65];   // padded, conflict-free
    __shared__ float norm_sm[NC];
    __shared__ int amLast;

    // Load v[b][lane][:] into registers
    float4 v4[16];
    const float4* vp = (const float4*)(&g_v[b][lane][0]);
    #pragma unroll
    for (int k = 0; k < 16; k++) v4[k] = vp[k];

    float4 s4[16];
    #pragma unroll
    for (int k = 0; k < 16; k++) s4[k] = make_float4(0.f, 0.f, 0.f, 0.f);

    const int l0 = chunk * (K3_WARPS * K3_LPW) + w * K3_LPW;
    const float* ub = u + ((size_t)b * LL + l0) * DIN;

    for (int j = 0; j < K3_LPW; j += 2) {
        float2 ra = ((const float2*)(ub + (size_t)j * DIN))[lane];
        float2 rb = ((const float2*)(ub + (size_t)(j + 1) * DIN))[lane];
        __syncwarp();
        ((float2*)u_buf[w][0])[lane] = ra;
        ((float2*)u_buf[w][1])[lane] = rb;
        __syncwarp();
        const float4* uA = (const float4*)u_buf[w][0];
        const float4* uB = (const float4*)u_buf[w][1];

        float lA0 = 0.f, lA1 = 0.f, lB0 = 0.f, lB1 = 0.f;
        #pragma unroll
        for (int k = 0; k < 16; k += 2) {
            float4 xA = uA[k], yA = uA[k + 1];
            float4 xB = uB[k], yB = uB[k + 1];
            lA0 = fmaf(xA.x, v4[k].x, lA0);     lA0 = fmaf(xA.y, v4[k].y, lA0);
            lA0 = fmaf(xA.z, v4[k].z, lA0);     lA0 = fmaf(xA.w, v4[k].w, lA0);
            lA1 = fmaf(yA.x, v4[k + 1].x, lA1); lA1 = fmaf(yA.y, v4[k + 1].y, lA1);
            lA1 = fmaf(yA.z, v4[k + 1].z, lA1); lA1 = fmaf(yA.w, v4[k + 1].w, lA1);
            lB0 = fmaf(xB.x, v4[k].x, lB0);     lB0 = fmaf(xB.y, v4[k].y, lB0);
            lB0 = fmaf(xB.z, v4[k].z, lB0);     lB0 = fmaf(xB.w, v4[k].w, lB0);
            lB1 = fmaf(yB.x, v4[k + 1].x, lB1); lB1 = fmaf(yB.y, v4[k + 1].y, lB1);
            lB1 = fmaf(yB.z, v4[k + 1].z, lB1); lB1 = fmaf(yB.w, v4[k + 1].w, lB1);
        }
        float eA = __expf(lA0 + lA1);
        float eB = __expf(lB0 + lB1);
        float sA = eA, sB = eB;
        #pragma unroll
        for (int off = 16; off; off >>= 1) {
            sA += __shfl_xor_sync(0xffffffffu, sA, off);
            sB += __shfl_xor_sync(0xffffffffu, sB, off);
        }
        float cA = __fdividef(eA, sA);
        float cB = __fdividef(eB, sB);

        #pragma unroll
        for (int k = 0; k < 16; k++) {
            float4 xA = uA[k], xB = uB[k];
            s4[k].x = fmaf(cA, xA.x, fmaf(cB, xB.x, s4[k].x));
            s4[k].y = fmaf(cA, xA.y, fmaf(cB, xB.y, s4[k].y));
            s4[k].z = fmaf(cA, xA.z, fmaf(cB, xB.z, s4[k].z));
            s4[k].w = fmaf(cA, xA.w, fmaf(cB, xB.w, s4[k].w));
        }
    }

    // dump register s into padded smem, cross-warp reduce, write partial
    #pragma unroll
    for (int k = 0; k < 16; k++) {
        s_blk[w][lane][4 * k + 0] = s4[k].x;
        s_blk[w][lane][4 * k + 1] = s4[k].y;
        s_blk[w][lane][4 * k + 2] = s4[k].z;
        s_blk[w][lane][4 * k + 3] = s4[k].w;
    }
    __syncthreads();

    float* outp = &g_s_part[b][chunk][0][0];
    for (int e = t; e < NC * DIN; e += 128) {
        int n = e >> 6, i = e & 63;
        outp[e] = s_blk[0][n][i] + s_blk[1][n][i] + s_blk[2][n][i] + s_blk[3][n][i];
    }

    // ---- last-block tail: epilogue for batch b ----
    __threadfence();
    __syncthreads();
    if (t == 0) amLast = (atomicAdd(&g_cnt3[iter - 1][b], 1) == K3_CHUNKS - 1);
    __syncthreads();
    if (!amLast) return;

    // reuse s_blk smem: s_sm = first 2048 floats, raw = next 512.
    // s_blk base is __align__(16); offsets 0 and 2048 floats (8192 B) keep it.
    float* s_sm   = &s_blk[0][0][0];          // [2048]
    float* raw_sm = s_sm + 2048;              // [512] (s_blk = 8320 floats total)

    for (int e = t; e < NC * DIN; e += 128) {
        float a = 0.f;
        const float* base = &g_s_part[b][0][0][0];
        #pragma unroll
        for (int c = 0; c < K3_CHUNKS; c++) a += base[(size_t)c * NC * DIN + e];
        s_sm[e] = a;                          // s[n][i], e = n*64+i
    }
    __syncthreads();
    for (int o = t; o < OUTD; o += 128) {     // coalesced over o
        const int n = o >> 4;
        float r = 0.f;
        #pragma unroll
        for (int i = 0; i < DIN; i++)
            r = fmaf(s_sm[n * DIN + i], W[(size_t)i * OUTD + o], r);
        raw_sm[o] = r;
    }
    __syncthreads();
    if (t < NC) {
        float s2 = 0.f;
        #pragma unroll
        for (int d = 0; d < DC; d++) {
            float r = raw_sm[t * DC + d];
            s2 = fmaf(r, r, s2);
        }
        norm_sm[t] = rsqrtf(s2 + EPSQ);
    }
    __syncthreads();

    if (iter == 1) {
        for (int e = t; e < NC * DIN; e += 128) {
            const int n = e >> 6, i = e & 63;
            const float4* Wr = (const float4*)(W + (size_t)i * OUTD + n * DC);
            const float4* Rr = (const float4*)(raw_sm + n * DC);
            float r = 0.f;
            #pragma unroll
            for (int q = 0; q < 4; q++) {
                float4 wv = Wr[q], rv = Rr[q];
                r = fmaf(wv.x, rv.x, r); r = fmaf(wv.y, rv.y, r);
                r = fmaf(wv.z, rv.z, r); r = fmaf(wv.w, rv.w, r);
            }
            g_v[b][n][i] = r * norm_sm[n];
        }
    } else {
        for (int o = t; o < OUTD; o += 128)
            out_final[(size_t)b * OUTD + o] = raw_sm[o] * norm_sm[o >> 4];
    }
    if (t == 0) g_cnt3[iter - 1][b] = 0;      // reset for next graph replay
}

// ---------------------------------------------------------------------------
extern "C" void kernel_launch(void* const* d_in, const int* in_sizes, int n_in,
                              void* d_out, int out_size) {
    const float* u = (const float*)d_in[0];   // [32, 2048, 64]
    const float* W = (const float*)d_in[1];   // [1, 64, 512]
    float* out = (float*)d_out;               // [32, 32, 16]

    k1_colsum<<<dim3(K1_CHUNKS, BB), 256>>>(u, W);            // colsum + v0
    k3_route<<<dim3(K3_CHUNKS, BB), 128>>>(u, W, out, 1);     // routing 1 + v1
    k3_route<<<dim3(K3_CHUNKS, BB), 128>>>(u, W, out, 2);     // routing 2 + out
}

// round 11
// speedup vs baseline: 1.2341x; 1.2341x over previous
#include <cuda_runtime.h>
#include <math.h>

// Problem constants
#define BB   32
#define LL   2048
#define DIN  64
#define NC   32
#define DC   16
#define OUTD 512           // NC*DC
#define EPSQ 1e-7f

#define K1_CHUNKS 16
#define K3_CHUNKS 8        // blocks per batch in routing pass (256 l's each)
#define K3_WARPS  4
#define K3_LPW    64       // l's per warp

// Scratch (static device allocations only — no cudaMalloc allowed)
__device__ float g_colsum_part[BB][K1_CHUNKS][DIN];
__device__ float g_s_part[BB][K3_CHUNKS][NC][DIN];   // 2 MB
__device__ float g_v[BB][NC][DIN];

// ---------------------------------------------------------------------------
// K1: column sums  colsum_part[b][chunk][i] = sum over 128 l's of u[b,l,i]
// grid (K1_CHUNKS, BB), 256 threads   (exact R7 form)
// ---------------------------------------------------------------------------
__global__ void k1_colsum(const float* __restrict__ u) {
    const int b = blockIdx.y, chunk = blockIdx.x;
    const int tid = threadIdx.x;
    const int col4 = tid & 15;
    const int g    = tid >> 4;

    const float4* up = (const float4*)(u + ((size_t)b * LL + (size_t)chunk * 128) * DIN);
    float4 acc = make_float4(0.f, 0.f, 0.f, 0.f);
    #pragma unroll
    for (int r = 0; r < 8; r++) {
        float4 x = up[(size_t)(g + r * 16) * 16 + col4];
        acc.x += x.x; acc.y += x.y; acc.z += x.z; acc.w += x.w;
    }
    __shared__ __align__(16) float4 red[16][16];
    red[g][col4] = acc;
    __syncthreads();
    if (tid < 16) {
        float4 s = red[0][tid];
        #pragma unroll
        for (int i = 1; i < 16; i++) {
            float4 x = red[i][tid];
            s.x += x.x; s.y += x.y; s.z += x.z; s.w += x.w;
        }
        ((float4*)g_colsum_part[b][chunk])[tid] = s;
    }
}

// ---------------------------------------------------------------------------
// K2: per-(b,n) epilogue. grid (NC, BB), 64 threads   (exact R7 form)
// ---------------------------------------------------------------------------
__global__ void __launch_bounds__(64, 16) k2_update(const float* __restrict__ W,
                                                    float* __restrict__ out_final,
                                                    int mode) {
    const int n = blockIdx.x, b = blockIdx.y;
    const int t = threadIdx.x;        // 0..63 == element index i

    __shared__ float s_sm[DIN];
    __shared__ float out_sm[DC];

    float a = 0.f;
    if (mode == 0) {
        #pragma unroll
        for (int c = 0; c < K1_CHUNKS; c++)
            a += g_colsum_part[b][c][t];
        a *= (1.0f / 32.0f);
    } else {
        #pragma unroll
        for (int c = 0; c < K3_CHUNKS; c++)
            a += g_s_part[b][c][n][t];
    }
    s_sm[t] = a;
    __syncthreads();

    if (t < 32) {
        float raw = 0.f;
        if (t < DC) {
            const float* Wc = W + (size_t)n * DC + t;   // W[i*512 + n*16 + t]
            #pragma unroll
            for (int i = 0; i < DIN; i++)
                raw = fmaf(s_sm[i], Wc[(size_t)i * OUTD], raw);
        }
        float s2 = raw * raw;
        #pragma unroll
        for (int off = 8; off; off >>= 1)
            s2 += __shfl_xor_sync(0xffffffffu, s2, off, 16);
        float o = raw * rsqrtf(s2 + EPSQ);
        if (t < DC) {
            if (mode == 2) out_final[(size_t)b * OUTD + (size_t)n * DC + t] = o;
            else           out_sm[t] = o;
        }
    }

    if (mode != 2) {
        __syncthreads();
        const float* Wr = W + (size_t)t * OUTD + (size_t)n * DC;
        float v = 0.f;
        #pragma unroll
        for (int d = 0; d < DC; d++)
            v = fmaf(Wr[d], out_sm[d], v);
        g_v[b][n][t] = v;
    }
}

// ---------------------------------------------------------------------------
// K3: fused routing pass, now 4 rows per iteration (4 independent
// logit/softmax/accumulate chains -> shuffle & MUFU latency overlapped).
// Per (b,l): logits[n] = u[l,:].v[n,:]; c = softmax_n; s[n,:] += c*u[l,:]
// Warp = 64 l's; lane n owns v[n] and s[n] in registers.
// grid (K3_CHUNKS, BB), 128 threads (4 warps).
// ---------------------------------------------------------------------------
__global__ void __launch_bounds__(128, 1) k3_route(const float* __restrict__ u) {
    const int b = blockIdx.y, chunk = blockIdx.x;
    const int w = threadIdx.x >> 5;
    const int lane = threadIdx.x & 31;       // lane == capsule index n

    __shared__ __align__(16) float u_buf[K3_WARPS][4][64];
    __shared__ __align__(16) float s_blk[K3_WARPS][NC][65];   // padded

    float4 v4[16];
    const float4* vp = (const float4*)(&g_v[b][lane][0]);
    #pragma unroll
    for (int k = 0; k < 16; k++) v4[k] = vp[k];

    float4 s4[16];
    #pragma unroll
    for (int k = 0; k < 16; k++) s4[k] = make_float4(0.f, 0.f, 0.f, 0.f);

    const int l0 = chunk * (K3_WARPS * K3_LPW) + w * K3_LPW;
    const float* ub = u + ((size_t)b * LL + l0) * DIN;

    for (int j = 0; j < K3_LPW; j += 4) {
        // cooperative row loads: 4 rows of 64 floats, one float2 per lane each
        float2 r0 = ((const float2*)(ub + (size_t)(j + 0) * DIN))[lane];
        float2 r1 = ((const float2*)(ub + (size_t)(j + 1) * DIN))[lane];
        float2 r2 = ((const float2*)(ub + (size_t)(j + 2) * DIN))[lane];
        float2 r3 = ((const float2*)(ub + (size_t)(j + 3) * DIN))[lane];
        __syncwarp();                         // WAR vs previous iteration's reads
        ((float2*)u_buf[w][0])[lane] = r0;
        ((float2*)u_buf[w][1])[lane] = r1;
        ((float2*)u_buf[w][2])[lane] = r2;
        ((float2*)u_buf[w][3])[lane] = r3;
        __syncwarp();

        const float4* ur[4] = { (const float4*)u_buf[w][0], (const float4*)u_buf[w][1],
                                (const float4*)u_buf[w][2], (const float4*)u_buf[w][3] };

        // 4 independent logit dots, 2 accumulators each
        float lg0[4], lg1[4];
        #pragma unroll
        for (int r = 0; r < 4; r++) { lg0[r] = 0.f; lg1[r] = 0.f; }
        #pragma unroll
        for (int k = 0; k < 16; k += 2) {
            #pragma unroll
            for (int r = 0; r < 4; r++) {
                float4 x = ur[r][k], y = ur[r][k + 1];
                lg0[r] = fmaf(x.x, v4[k].x, lg0[r]);     lg0[r] = fmaf(x.y, v4[k].y, lg0[r]);
                lg0[r] = fmaf(x.z, v4[k].z, lg0[r]);     lg0[r] = fmaf(x.w, v4[k].w, lg0[r]);
                lg1[r] = fmaf(y.x, v4[k + 1].x, lg1[r]); lg1[r] = fmaf(y.y, v4[k + 1].y, lg1[r]);
                lg1[r] = fmaf(y.z, v4[k + 1].z, lg1[r]); lg1[r] = fmaf(y.w, v4[k + 1].w, lg1[r]);
            }
        }

        // 4 overlapped softmaxes over the 32 lanes (no max-subtract; |logit| << 88)
        float ex[4], sm[4], cc[4];
        #pragma unroll
        for (int r = 0; r < 4; r++) { ex[r] = __expf(lg0[r] + lg1[r]); sm[r] = ex[r]; }
        #pragma unroll
        for (int off = 16; off; off >>= 1) {
            #pragma unroll
            for (int r = 0; r < 4; r++)
                sm[r] += __shfl_xor_sync(0xffffffffu, sm[r], off);
        }
        #pragma unroll
        for (int r = 0; r < 4; r++) cc[r] = __fdividef(ex[r], sm[r]);

        // accumulate s[n,:] += sum_r cc[r] * u_r[:]
        #pragma unroll
        for (int k = 0; k < 16; k++) {
            float4 acc = s4[k];
            #pragma unroll
            for (int r = 0; r < 4; r++) {
                float4 x = ur[r][k];
                acc.x = fmaf(cc[r], x.x, acc.x);
                acc.y = fmaf(cc[r], x.y, acc.y);
                acc.z = fmaf(cc[r], x.z, acc.z);
                acc.w = fmaf(cc[r], x.w, acc.w);
            }
            s4[k] = acc;
        }
    }

    // dump register s into padded smem (stride 65 -> conflict-free)
    #pragma unroll
    for (int k = 0; k < 16; k++) {
        s_blk[w][lane][4 * k + 0] = s4[k].x;
        s_blk[w][lane][4 * k + 1] = s4[k].y;
        s_blk[w][lane][4 * k + 2] = s4[k].z;
        s_blk[w][lane][4 * k + 3] = s4[k].w;
    }
    __syncthreads();

    // cross-warp reduce, deterministic, coalesced write of this block's partial
    float* outp = (float*)g_s_part[b][chunk];
    for (int e = threadIdx.x; e < NC * DIN; e += 128) {
        int n = e >> 6, i = e & 63;
        outp[e] = s_blk[0][n][i] + s_blk[1][n][i] + s_blk[2][n][i] + s_blk[3][n][i];
    }
}

// ---------------------------------------------------------------------------
extern "C" void kernel_launch(void* const* d_in, const int* in_sizes, int n_in,
                              void* d_out, int out_size) {
    const float* u = (const float*)d_in[0];   // [32, 2048, 64]
    const float* W = (const float*)d_in[1];   // [1, 64, 512]
    float* out = (float*)d_out;               // [32, 32, 16]

    // iteration 0: uniform c -> colsum path
    k1_colsum<<<dim3(K1_CHUNKS, BB), 256>>>(u);
    k2_update<<<dim3(NC, BB), 64>>>(W, out, 0);   // outputs0 + v0
    // iteration 1
    k3_route<<<dim3(K3_CHUNKS, BB), 128>>>(u);
    k2_update<<<dim3(NC, BB), 64>>>(W, out, 1);   // outputs1 + v1
    // iteration 2 (final)
    k3_route<<<dim3(K3_CHUNKS, BB), 128>>>(u);
    k2_update<<<dim3(NC, BB), 64>>>(W, out, 2);   // outputs2 -> d_out
}